// round 13
// baseline (speedup 1.0000x reference)
#include <cuda_runtime.h>

// Grouped 3-tap width conv with cyclic rolls, fp32. Single kernel node.
// Grid = 16 k-tiles x 7 heights = 112 blocks, 1024 threads (32 warps).
// Warp-autonomous: each warp streams its private 16-i weight slice via
// triple-buffered cp.async.bulk + private mbarrier; zero block syncs in the
// mainloop. o-paired f32x2 taps. Epilogue reduce overlays dead weight smem.
//
// y[o,k,n,m] = sum_{i,j} f[o,i,m+j] * w[i,k,j],  f[1..7] = width-rolled x row,
// f[0]=f[8]=0 (taps dropped); height roll baked into the final store index.

#define THREADS  1024
#define NCHK     4                 // chunks; 4 i-rows per warp per chunk
#define WROW     384               // bytes per weight row (96 floats)
#define NBUF     3
#define WSLICE   (NBUF * 4 * WROW) // 4608 B per-warp weight slice

#define OFF_IN   0
#define SZ_IN    (512 * 64)        // 32768: input row i = 7 float2 (x0,x1) + pad
#define OFF_W    SZ_IN
#define SZ_W     (32 * WSLICE)     // 147456
#define OFF_MB   (OFF_W + SZ_W)    // 180224: 32 warps x 3 mbarriers
#define SMEM_TOT (OFF_MB + 32 * 3 * 8)     // 180992
#define OFF_RED  OFF_W             // reduce buffer overlays dead weight region

typedef unsigned long long ull;

__device__ __forceinline__ ull ffma2(ull a, ull b, ull c)
{
    ull d;
    asm("fma.rn.f32x2 %0, %1, %2, %3;" : "=l"(d) : "l"(a), "l"(b), "l"(c));
    return d;
}
__device__ __forceinline__ ull dup2(float v)
{
    ull d;
    asm("mov.b64 %0, {%1, %1};" : "=l"(d) : "f"(v));
    return d;
}
__device__ __forceinline__ void bulk384(unsigned dst, const void* src, unsigned mbar)
{
    asm volatile(
        "cp.async.bulk.shared::cluster.global.mbarrier::complete_tx::bytes "
        "[%0], [%1], 384, [%2];"
        :: "r"(dst), "l"(src), "r"(mbar) : "memory");
}
__device__ __forceinline__ void mbar_init(unsigned mbar, unsigned cnt)
{
    asm volatile("mbarrier.init.shared.b64 [%0], %1;" :: "r"(mbar), "r"(cnt) : "memory");
}
__device__ __forceinline__ void mbar_expect(unsigned mbar, unsigned bytes)
{
    asm volatile("mbarrier.arrive.expect_tx.shared.b64 _, [%0], %1;"
                 :: "r"(mbar), "r"(bytes) : "memory");
}
__device__ __forceinline__ void mbar_wait(unsigned mbar, unsigned parity)
{
    asm volatile(
        "{\n\t"
        ".reg .pred P;\n\t"
        "WL_%=:\n\t"
        "mbarrier.try_wait.parity.acquire.cta.shared::cta.b64 P, [%0], %1, 0x989680;\n\t"
        "@P bra.uni WD_%=;\n\t"
        "bra.uni WL_%=;\n\t"
        "WD_%=:\n\t"
        "}"
        :: "r"(mbar), "r"(parity) : "memory");
}

__global__ __launch_bounds__(THREADS, 1) void conv_wa2(const float* __restrict__ x,
                                                       const float* __restrict__ w,
                                                       float* __restrict__ out)
{
    extern __shared__ char sm[];
    const unsigned sb = (unsigned)__cvta_generic_to_shared(sm);
    const int tid = threadIdx.x, warp = tid >> 5, lane = tid & 31;
    const int kb  = blockIdx.x, n = blockIdx.y, k0 = kb * 32;

    const unsigned mbW = sb + OFF_MB + warp * 24;   // 3 mbarriers per warp

    // ---- init mbarriers (count 4: lanes 0-3 arrive via expect_tx) ----
    if (tid < 96) mbar_init(sb + OFF_MB + tid * 8, 4);
    __syncthreads();

    // ---- per-warp bulk issue of chunks 0..2 into the private slice ----
    const unsigned wSl = sb + OFF_W + warp * WSLICE;
    if (lane < 4) {
#pragma unroll
        for (int c = 0; c < 3; c++) {
            mbar_expect(mbW + c * 8, 384);
            bulk384(wSl + c * (4 * WROW) + lane * WROW,
                    w + (c * 128 + warp * 4 + lane) * 1536 + kb * 96,
                    mbW + c * 8);
        }
    }

    // ---- input staging: thread = row r = o*512 + i (7 LDG + 7 STS, no divides) ----
    {
        const int o = tid >> 9, i = tid & 511;
        const float* src = x + tid * 49 + n * 7;
        float v0 = src[0], v1 = src[1], v2 = src[2], v3 = src[3];
        float v4 = src[4], v5 = src[5], v6 = src[6];
        char* row = sm + OFF_IN + i * 64 + o * 4;   // slot (u-1)*8 + o*4
        *reinterpret_cast<float*>(row)      = v6;   // j=6 -> u=1  (width roll +1)
        *reinterpret_cast<float*>(row + 8)  = v0;   // j=0 -> u=2
        *reinterpret_cast<float*>(row + 16) = v1;
        *reinterpret_cast<float*>(row + 24) = v2;
        *reinterpret_cast<float*>(row + 32) = v3;
        *reinterpret_cast<float*>(row + 40) = v4;
        *reinterpret_cast<float*>(row + 48) = v5;   // j=5 -> u=7
    }
    __syncthreads();                     // input visible (only pre-epilogue block sync)

    // ---- compute: lane = channel k0+lane; A[m] = (y_o0, y_o1) pairs ----
    ull A[7];
#pragma unroll
    for (int m = 0; m < 7; m++) A[m] = 0ull;

#pragma unroll 1
    for (int c = 0; c < NCHK; c++) {
        const int b = (c < 3) ? c : 0;
        mbar_wait(mbW + b * 8, (c < 3) ? 0 : 1);       // warp-private wait

        const char* wp = sm + OFF_W + warp * WSLICE + b * (4 * WROW) + lane * 12;
        const char* ip = sm + OFF_IN + ((c * 128 + warp * 4) << 6);

#pragma unroll
        for (int t = 0; t < 4; t++) {
            const char* ib = ip + t * 64;              // warp-uniform -> broadcast
            ulonglong2 L0 = *reinterpret_cast<const ulonglong2*>(ib);        // f1,f2
            ulonglong2 L1 = *reinterpret_cast<const ulonglong2*>(ib + 16);   // f3,f4
            ulonglong2 L2 = *reinterpret_cast<const ulonglong2*>(ib + 32);   // f5,f6
            ull        p7 = *reinterpret_cast<const ull*>(ib + 48);          // f7
            const float* wr = reinterpret_cast<const float*>(wp + t * WROW);
            ull W0 = dup2(wr[0]), W1 = dup2(wr[1]), W2 = dup2(wr[2]);
            ull p1 = L0.x, p2 = L0.y, p3 = L1.x, p4 = L1.y, p5 = L2.x, p6 = L2.y;

            // A[m] += f[m]*W0 + f[m+1]*W1 + f[m+2]*W2  (f0 = f8 = 0 dropped)
            A[0] = ffma2(p1, W1, A[0]); A[0] = ffma2(p2, W2, A[0]);
            A[1] = ffma2(p1, W0, A[1]); A[1] = ffma2(p2, W1, A[1]); A[1] = ffma2(p3, W2, A[1]);
            A[2] = ffma2(p2, W0, A[2]); A[2] = ffma2(p3, W1, A[2]); A[2] = ffma2(p4, W2, A[2]);
            A[3] = ffma2(p3, W0, A[3]); A[3] = ffma2(p4, W1, A[3]); A[3] = ffma2(p5, W2, A[3]);
            A[4] = ffma2(p4, W0, A[4]); A[4] = ffma2(p5, W1, A[4]); A[4] = ffma2(p6, W2, A[4]);
            A[5] = ffma2(p5, W0, A[5]); A[5] = ffma2(p6, W1, A[5]); A[5] = ffma2(p7, W2, A[5]);
            A[6] = ffma2(p6, W0, A[6]); A[6] = ffma2(p7, W1, A[6]);
        }

        if (c == 0) {                    // recycle buf0 for chunk 3 (warp-local)
            __syncwarp();
            if (lane < 4) {
                mbar_expect(mbW, 384);
                bulk384(wSl + lane * WROW,
                        w + (3 * 128 + warp * 4 + lane) * 1536 + kb * 96,
                        mbW);
            }
        }
    }

    // ---- epilogue: overlay reduce buffer on dead weight smem ----
    __syncthreads();                     // all warps done reading weight smem
    float2* red = reinterpret_cast<float2*>(sm + OFF_RED);
#pragma unroll
    for (int m = 0; m < 7; m++)
        red[warp * 224 + lane * 7 + m] = *reinterpret_cast<float2*>(&A[m]);
    __syncthreads();

    if (tid < 224) {                     // t = k*7 + m; reads lane-stride 8B
        float sx = 0.f, sy = 0.f;
#pragma unroll
        for (int is = 0; is < 32; is++) {
            float2 v = red[is * 224 + tid];
            sx += v.x; sy += v.y;
        }
        int k = tid / 7, m = tid - k * 7;
        int nOut = n + 1; if (nOut == 7) nOut = 0;     // height roll +1
        out[(k0 + k) * 49 + nOut * 7 + m]       = sx;  // group 0
        out[(512 + k0 + k) * 49 + nOut * 7 + m] = sy;  // group 1
    }
}

extern "C" void kernel_launch(void* const* d_in, const int* in_sizes, int n_in,
                              void* d_out, int out_size)
{
    const float* x = (const float*)d_in[0];
    const float* w = (const float*)d_in[1];
    float* out = (float*)d_out;

    cudaFuncSetAttribute(conv_wa2, cudaFuncAttributeMaxDynamicSharedMemorySize, SMEM_TOT);
    conv_wa2<<<dim3(16, 7), THREADS, SMEM_TOT>>>(x, w, out);
}

// round 14
// speedup vs baseline: 1.5199x; 1.5199x over previous
#include <cuda_runtime.h>

// Grouped 3-tap width conv with cyclic rolls, fp32. Single kernel node.
// Grid = 16 k-tiles x 7 heights = 112 blocks, 512 threads (16 warps).
// Weights: gmem -> registers, double-buffered per 8-i chunk (coalesced
// LDG.32x3 per lane; each lane's 3 taps are contiguous at w[i*1536+k*3]).
// No weight smem, no bulk-copy, no mbarriers. Input in smem (broadcast LDS),
// o-paired f32x2 taps, conflict-free epilogue reduce.
//
// y[o,k,n,m] = sum_{i,j} f[o,i,m+j] * w[i,k,j],  f[1..7] = width-rolled x row,
// f[0]=f[8]=0 (taps dropped); height roll baked into the final store index.

#define THREADS  512

#define OFF_IN   0
#define SZ_IN    (512 * 64)        // input row i = 7 float2 (x0,x1) slots + pad
#define SMEM_TOT SZ_IN             // 32768 B; epilogue reduce overlays this
#define OFF_RED  0

typedef unsigned long long ull;

__device__ __forceinline__ ull ffma2(ull a, ull b, ull c)
{
    ull d;
    asm("fma.rn.f32x2 %0, %1, %2, %3;" : "=l"(d) : "l"(a), "l"(b), "l"(c));
    return d;
}
__device__ __forceinline__ ull dup2(float v)
{
    ull d;
    asm("mov.b64 %0, {%1, %1};" : "=l"(d) : "f"(v));
    return d;
}

__global__ __launch_bounds__(THREADS, 1) void conv_reg(const float* __restrict__ x,
                                                       const float* __restrict__ w,
                                                       float* __restrict__ out)
{
    extern __shared__ char sm[];
    const int tid = threadIdx.x, warp = tid >> 5, lane = tid & 31;
    const int kb  = blockIdx.x, n = blockIdx.y, k0 = kb * 32;

    // ---- input staging: coalesced element walk (14 x LDG.32 per thread) ----
    {
        int r = tid / 7;                 // r = o*512 + i
        int j = tid - r * 7;             // source width position
        const int nbase = n * 7;
#pragma unroll
        for (int k = 0; k < 14; k++) {
            float v = x[r * 49 + nbase + j];
            int u = (j == 6) ? 1 : (j + 2);            // width roll +1
            int o = r >> 9, i = r & 511;
            *reinterpret_cast<float*>(sm + OFF_IN + i * 64 + (u - 1) * 8 + o * 4) = v;
            j += 1; r += 73;
            if (j == 7) { j = 0; r += 1; }
        }
    }

    // ---- weight register pipeline: 4 chunks of 8 i, double-buffered ----
    const int iB = warp * 32;            // warp-private i slice
    const float* wl = w + (long)iB * 1536 + (k0 + lane) * 3;

    float a0[8], a1[8], a2[8];           // buffer A
    float b0[8], b1[8], b2[8];           // buffer B

#define LOADW(d0, d1, d2, c) do { \
        const float* p_ = wl + (c) * (8 * 1536); \
        _Pragma("unroll") \
        for (int t = 0; t < 8; t++) { \
            d0[t] = p_[t * 1536]; \
            d1[t] = p_[t * 1536 + 1]; \
            d2[t] = p_[t * 1536 + 2]; \
        } \
    } while (0)

    LOADW(a0, a1, a2, 0);                // chunks 0 and 1 in flight before the
    LOADW(b0, b1, b2, 1);                // input barrier

    __syncthreads();                     // input smem visible

    ull A[7];
#pragma unroll
    for (int m = 0; m < 7; m++) A[m] = 0ull;

#define COMPUTE(c, s0, s1, s2) do { \
        const char* ip_ = sm + OFF_IN + ((iB + (c) * 8) << 6); \
        _Pragma("unroll") \
        for (int t = 0; t < 8; t++) { \
            const char* ib = ip_ + t * 64; \
            ulonglong2 L0 = *reinterpret_cast<const ulonglong2*>(ib);       /* f1,f2 */ \
            ulonglong2 L1 = *reinterpret_cast<const ulonglong2*>(ib + 16);  /* f3,f4 */ \
            ulonglong2 L2 = *reinterpret_cast<const ulonglong2*>(ib + 32);  /* f5,f6 */ \
            ull        p7 = *reinterpret_cast<const ull*>(ib + 48);         /* f7 */ \
            ull W0 = dup2(s0[t]), W1 = dup2(s1[t]), W2 = dup2(s2[t]); \
            ull p1 = L0.x, p2 = L0.y, p3 = L1.x, p4 = L1.y, p5 = L2.x, p6 = L2.y; \
            A[0] = ffma2(p1, W1, A[0]); A[0] = ffma2(p2, W2, A[0]); \
            A[1] = ffma2(p1, W0, A[1]); A[1] = ffma2(p2, W1, A[1]); A[1] = ffma2(p3, W2, A[1]); \
            A[2] = ffma2(p2, W0, A[2]); A[2] = ffma2(p3, W1, A[2]); A[2] = ffma2(p4, W2, A[2]); \
            A[3] = ffma2(p3, W0, A[3]); A[3] = ffma2(p4, W1, A[3]); A[3] = ffma2(p5, W2, A[3]); \
            A[4] = ffma2(p4, W0, A[4]); A[4] = ffma2(p5, W1, A[4]); A[4] = ffma2(p6, W2, A[4]); \
            A[5] = ffma2(p5, W0, A[5]); A[5] = ffma2(p6, W1, A[5]); A[5] = ffma2(p7, W2, A[5]); \
            A[6] = ffma2(p6, W0, A[6]); A[6] = ffma2(p7, W1, A[6]); \
        } \
    } while (0)

    COMPUTE(0, a0, a1, a2);
    LOADW(a0, a1, a2, 2);                // refill A while B is ready
    COMPUTE(1, b0, b1, b2);
    LOADW(b0, b1, b2, 3);
    COMPUTE(2, a0, a1, a2);
    COMPUTE(3, b0, b1, b2);

    // ---- epilogue: conflict-free reduce (overlays dead input smem) ----
    __syncthreads();                     // everyone done reading input smem
    float2* red = reinterpret_cast<float2*>(sm + OFF_RED);
#pragma unroll
    for (int m = 0; m < 7; m++)
        red[warp * 224 + lane * 7 + m] = *reinterpret_cast<float2*>(&A[m]);
    __syncthreads();

    if (tid < 224) {                     // t = k*7 + m; reads lane-stride 8B
        float sx = 0.f, sy = 0.f;
#pragma unroll
        for (int is = 0; is < 16; is++) {
            float2 v = red[is * 224 + tid];
            sx += v.x; sy += v.y;
        }
        int k = tid / 7, m = tid - k * 7;
        int nOut = n + 1; if (nOut == 7) nOut = 0;     // height roll +1
        out[(k0 + k) * 49 + nOut * 7 + m]       = sx;  // group 0
        out[(512 + k0 + k) * 49 + nOut * 7 + m] = sy;  // group 1
    }
}

extern "C" void kernel_launch(void* const* d_in, const int* in_sizes, int n_in,
                              void* d_out, int out_size)
{
    const float* x = (const float*)d_in[0];
    const float* w = (const float*)d_in[1];
    float* out = (float*)d_out;

    conv_reg<<<dim3(16, 7), THREADS, SMEM_TOT>>>(x, w, out);
}

// round 15
// speedup vs baseline: 1.5598x; 1.0262x over previous
#include <cuda_runtime.h>

// Grouped 3-tap width conv with cyclic rolls, fp32. Single kernel node.
// Grid = 16 k-tiles x 7 heights = 112 blocks, 512 threads (16 warps).
// Weights: gmem -> registers, TRIPLE-buffered (chunks 0-2 prefetched before
// the input barrier; chunk 3 issued right after compute-0 -> all weight
// latencies hidden). Input in smem (broadcast LDS), o-paired f32x2 taps,
// conflict-free epilogue reduce.
//
// y[o,k,n,m] = sum_{i,j} f[o,i,m+j] * w[i,k,j],  f[1..7] = width-rolled x row,
// f[0]=f[8]=0 (taps dropped); height roll baked into the final store index.

#define THREADS  512

#define OFF_IN   0
#define SZ_IN    (512 * 64)        // input row i = 7 float2 (x0,x1) slots + pad
#define SMEM_TOT SZ_IN             // 32768 B; epilogue reduce overlays this
#define OFF_RED  0

typedef unsigned long long ull;

__device__ __forceinline__ ull ffma2(ull a, ull b, ull c)
{
    ull d;
    asm("fma.rn.f32x2 %0, %1, %2, %3;" : "=l"(d) : "l"(a), "l"(b), "l"(c));
    return d;
}
__device__ __forceinline__ ull dup2(float v)
{
    ull d;
    asm("mov.b64 %0, {%1, %1};" : "=l"(d) : "f"(v));
    return d;
}

__global__ __launch_bounds__(THREADS, 1) void conv_reg3(const float* __restrict__ x,
                                                        const float* __restrict__ w,
                                                        float* __restrict__ out)
{
    extern __shared__ char sm[];
    const int tid = threadIdx.x, warp = tid >> 5, lane = tid & 31;
    const int kb  = blockIdx.x, n = blockIdx.y, k0 = kb * 32;

    // ---- input staging: coalesced element walk (14 x LDG.32 per thread) ----
    {
        int r = tid / 7;                 // r = o*512 + i
        int j = tid - r * 7;             // source width position
        const int nbase = n * 7;
#pragma unroll
        for (int k = 0; k < 14; k++) {
            float v = x[r * 49 + nbase + j];
            int u = (j == 6) ? 1 : (j + 2);            // width roll +1
            int o = r >> 9, i = r & 511;
            *reinterpret_cast<float*>(sm + OFF_IN + i * 64 + (u - 1) * 8 + o * 4) = v;
            j += 1; r += 73;
            if (j == 7) { j = 0; r += 1; }
        }
    }

    // ---- weight register pipeline: 4 chunks of 8 i, 3 buffers ----
    const int iB = warp * 32;            // warp-private i slice
    const float* wl = w + (long)iB * 1536 + (k0 + lane) * 3;

    float a0[8], a1[8], a2[8];           // buffer A
    float b0[8], b1[8], b2[8];           // buffer B
    float c0[8], c1[8], c2[8];           // buffer C

#define LOADW(d0, d1, d2, c) do { \
        const float* p_ = wl + (c) * (8 * 1536); \
        _Pragma("unroll") \
        for (int t = 0; t < 8; t++) { \
            d0[t] = p_[t * 1536]; \
            d1[t] = p_[t * 1536 + 1]; \
            d2[t] = p_[t * 1536 + 2]; \
        } \
    } while (0)

    LOADW(a0, a1, a2, 0);                // chunks 0..2 all in flight under the
    LOADW(b0, b1, b2, 1);                // staging latency shadow
    LOADW(c0, c1, c2, 2);

    __syncthreads();                     // input smem visible

    ull A[7];
#pragma unroll
    for (int m = 0; m < 7; m++) A[m] = 0ull;

#define COMPUTE(c, s0, s1, s2) do { \
        const char* ip_ = sm + OFF_IN + ((iB + (c) * 8) << 6); \
        _Pragma("unroll") \
        for (int t = 0; t < 8; t++) { \
            const char* ib = ip_ + t * 64; \
            ulonglong2 L0 = *reinterpret_cast<const ulonglong2*>(ib);       /* f1,f2 */ \
            ulonglong2 L1 = *reinterpret_cast<const ulonglong2*>(ib + 16);  /* f3,f4 */ \
            ulonglong2 L2 = *reinterpret_cast<const ulonglong2*>(ib + 32);  /* f5,f6 */ \
            ull        p7 = *reinterpret_cast<const ull*>(ib + 48);         /* f7 */ \
            ull W0 = dup2(s0[t]), W1 = dup2(s1[t]), W2 = dup2(s2[t]); \
            ull p1 = L0.x, p2 = L0.y, p3 = L1.x, p4 = L1.y, p5 = L2.x, p6 = L2.y; \
            A[0] = ffma2(p1, W1, A[0]); A[0] = ffma2(p2, W2, A[0]); \
            A[1] = ffma2(p1, W0, A[1]); A[1] = ffma2(p2, W1, A[1]); A[1] = ffma2(p3, W2, A[1]); \
            A[2] = ffma2(p2, W0, A[2]); A[2] = ffma2(p3, W1, A[2]); A[2] = ffma2(p4, W2, A[2]); \
            A[3] = ffma2(p3, W0, A[3]); A[3] = ffma2(p4, W1, A[3]); A[3] = ffma2(p5, W2, A[3]); \
            A[4] = ffma2(p4, W0, A[4]); A[4] = ffma2(p5, W1, A[4]); A[4] = ffma2(p6, W2, A[4]); \
            A[5] = ffma2(p5, W0, A[5]); A[5] = ffma2(p6, W1, A[5]); A[5] = ffma2(p7, W2, A[5]); \
            A[6] = ffma2(p6, W0, A[6]); A[6] = ffma2(p7, W1, A[6]); \
        } \
    } while (0)

    COMPUTE(0, a0, a1, a2);
    LOADW(a0, a1, a2, 3);                // chunk 3 hides behind compute 1+2
    COMPUTE(1, b0, b1, b2);
    COMPUTE(2, c0, c1, c2);
    COMPUTE(3, a0, a1, a2);

    // ---- epilogue: conflict-free reduce (overlays dead input smem) ----
    __syncthreads();                     // everyone done reading input smem
    float2* red = reinterpret_cast<float2*>(sm + OFF_RED);
#pragma unroll
    for (int m = 0; m < 7; m++)
        red[warp * 224 + lane * 7 + m] = *reinterpret_cast<float2*>(&A[m]);
    __syncthreads();

    if (tid < 224) {                     // t = k*7 + m; reads lane-stride 8B
        float sx = 0.f, sy = 0.f;
#pragma unroll
        for (int is = 0; is < 16; is++) {
            float2 v = red[is * 224 + tid];
            sx += v.x; sy += v.y;
        }
        int k = tid / 7, m = tid - k * 7;
        int nOut = n + 1; if (nOut == 7) nOut = 0;     // height roll +1
        out[(k0 + k) * 49 + nOut * 7 + m]       = sx;  // group 0
        out[(512 + k0 + k) * 49 + nOut * 7 + m] = sy;  // group 1
    }
}

extern "C" void kernel_launch(void* const* d_in, const int* in_sizes, int n_in,
                              void* d_out, int out_size)
{
    const float* x = (const float*)d_in[0];
    const float* w = (const float*)d_in[1];
    float* out = (float*)d_out;

    conv_reg3<<<dim3(16, 7), THREADS, SMEM_TOT>>>(x, w, out);
}